// round 6
// baseline (speedup 1.0000x reference)
#include <cuda_runtime.h>
#include <math.h>
#include <stdint.h>

#define CS   8
#define GRID 152
#define TPB  512
#define HID  256
#define ENCL 16
#define DECL 25
#define NV   28

typedef unsigned long long ull;

// tables built by CTAs 8..51, layout [t][unit][gate]
__device__ float g_pre[ENCL * 1024];
__device__ float g_tab[NV * 1024];
__device__ int   g_flag[ENCL + NV];          // zero at load; reset at kernel end

// ---------------- smem layout (float offsets) ----------------
#define O_H3B   0               // 3 x 256 h buffers
#define O_CF    768             // cfull [256]
#define O_PRE   1024            // [16][32][4] = 2048
#define O_TAB   3072            // [28][32][4] = 3584
#define O_OW    6656            // out_W rows, stride 264 -> 7392
#define O_CATH  14048           // [40]
#define O_CATC  14088           // [40]
#define O_CNEW  14128           // [32]
#define O_WMAX  14160           // 8 x ull
#define O_TAGS  14176           // 24 ints
#define SMEM_FLOATS 14200
#define SMEM_BYTES  (SMEM_FLOATS * 4)

// ---------------- PTX helpers ----------------
__device__ __forceinline__ uint32_t smem_u32(const void* p) {
    uint32_t a;
    asm("{ .reg .u64 t; cvta.to.shared.u64 t, %1; cvt.u32.u64 %0, t; }" : "=r"(a) : "l"(p));
    return a;
}
__device__ __forceinline__ uint32_t mapa_u32(uint32_t a, uint32_t rank) {
    uint32_t r;
    asm("mapa.shared::cluster.u32 %0, %1, %2;" : "=r"(r) : "r"(a), "r"(rank));
    return r;
}
__device__ __forceinline__ void st_cluster_b64(uint32_t addr, ull v) {
    asm volatile("st.shared::cluster.b64 [%0], %1;" :: "r"(addr), "l"(v) : "memory");
}
__device__ __forceinline__ void st_rel_cluster_u32(uint32_t addr, uint32_t v) {
    asm volatile("st.release.cluster.shared::cluster.u32 [%0], %1;" :: "r"(addr), "r"(v) : "memory");
}
__device__ __forceinline__ int ld_vol_s32(uint32_t addr) {
    int v;
    asm volatile("ld.volatile.shared.s32 %0, [%1];" : "=r"(v) : "r"(addr) : "memory");
    return v;
}
__device__ __forceinline__ int ld_acq_gpu(const int* p) {
    int v;
    asm volatile("ld.acquire.gpu.global.s32 %0, [%1];" : "=r"(v) : "l"(p) : "memory");
    return v;
}
__device__ __forceinline__ void st_rel_gpu(int* p, int v) {
    asm volatile("st.release.gpu.global.s32 [%0], %1;" :: "l"(p), "r"(v) : "memory");
}
__device__ __forceinline__ void pf_l2(const void* p) {
    asm volatile("prefetch.global.L2 [%0];" :: "l"(p));
}
__device__ __forceinline__ void cluster_bar() {
    asm volatile("barrier.cluster.arrive.aligned;" ::: "memory");
    asm volatile("barrier.cluster.wait.aligned;" ::: "memory");
}
__device__ __forceinline__ void wait_tags(uint32_t tagsb, int slot, int s8, int n) {
    uint32_t a = tagsb + (uint32_t)((slot * 8 + s8) * 4);
    while (!__all_sync(0xffffffffu, ld_vol_s32(a) >= n)) { }
}
__device__ __forceinline__ void ffma2(ull &acc, ull a, ull b) {
    asm("fma.rn.f32x2 %0, %1, %2, %0;" : "+l"(acc) : "l"(a), "l"(b));
}
__device__ __forceinline__ float ups(ull a) {
    float lo, hi;
    asm("mov.b64 {%0,%1}, %2;" : "=f"(lo), "=f"(hi) : "l"(a));
    return lo + hi;
}
__device__ __forceinline__ ull pack2(float lo, float hi) {
    ull r;
    asm("mov.b64 %0, {%1,%2};" : "=l"(r) : "f"(lo), "f"(hi));
    return r;
}
__device__ __forceinline__ float sigf(float x) { return __fdividef(1.f, 1.f + __expf(-x)); }
__device__ __forceinline__ float tanhfast(float x) {
    float t = __expf(-2.f * fabsf(x));
    return copysignf(__fdividef(1.f - t, 1.f + t), x);
}
__device__ __forceinline__ float red32(float s) {
#pragma unroll
    for (int o = 16; o > 0; o >>= 1) s += __shfl_xor_sync(0xffffffffu, s, o);
    return s;
}
__device__ __forceinline__ float dot8(float4 a0, float4 a1, float4 b0, float4 b1) {
    return a0.x*b0.x + a0.y*b0.y + a0.z*b0.z + a0.w*b0.w
         + a1.x*b1.x + a1.y*b1.y + a1.z*b1.z + a1.w*b1.w;
}
__device__ __forceinline__ void load_wrows(const float* W, int RA, int RB, int s8,
                                           ull* wA, ull* wB) {
#pragma unroll
    for (int kk = 0; kk < 8; kk++) {
        int k = (kk + s8) & 7;
        ulonglong2 a = *(const ulonglong2*)(W + RA * HID + s8 * 32 + k * 4);
        ulonglong2 b = *(const ulonglong2*)(W + RB * HID + s8 * 32 + k * 4);
        wA[2*kk] = a.x; wA[2*kk+1] = a.y;
        wB[2*kk] = b.x; wB[2*kk+1] = b.y;
    }
}
__device__ __forceinline__ void dual_dot(const float* v, int s8,
                                         const ull* wA, const ull* wB,
                                         float &sA, float &sB) {
    ull aA = 0ull, aB = 0ull;
#pragma unroll
    for (int kk = 0; kk < 8; kk++) {
        int k = (kk + s8) & 7;
        ulonglong2 x = *(const ulonglong2*)(v + s8 * 32 + k * 4);
        ffma2(aA, wA[2*kk], x.x); ffma2(aA, wA[2*kk+1], x.y);
        ffma2(aB, wB[2*kk], x.x); ffma2(aB, wB[2*kk+1], x.y);
    }
    float fA = ups(aA), fB = ups(aB);
#pragma unroll
    for (int o = 1; o < 8; o <<= 1) {
        fA += __shfl_xor_sync(0xffffffffu, fA, o);
        fB += __shfl_xor_sync(0xffffffffu, fB, o);
    }
    sA = fA; sB = fB;
}
__device__ __forceinline__ float one_dot(const float* v, const float* wrow, int s8) {
    ull acc = 0ull;
#pragma unroll
    for (int kk = 0; kk < 8; kk++) {
        int k = (kk + s8) & 7;
        ulonglong2 x = *(const ulonglong2*)(v + s8 * 32 + k * 4);
        ulonglong2 wv = *(const ulonglong2*)(wrow + s8 * 32 + k * 4);
        ffma2(acc, wv.x, x.x); ffma2(acc, wv.y, x.y);
    }
    float f = ups(acc);
#pragma unroll
    for (int o = 1; o < 8; o <<= 1) f += __shfl_xor_sync(0xffffffffu, f, o);
    return f;
}

__global__ void __launch_bounds__(TPB, 1) __cluster_dims__(CS, 1, 1) vae_kernel(
    const int* data, const int* data_c, const int* target_c, const float* cond_emb,
    const float* enc_emb, const float* enc_Wih, const float* enc_Whh,
    const float* enc_bih, const float* enc_bhh,
    const float* hmu_W, const float* hmu_b, const float* cmu_W, const float* cmu_b,
    const float* fc1_W, const float* fc1_b, const float* fc2_W, const float* fc2_b,
    const float* dec_emb, const float* dec_Wih, const float* dec_Whh,
    const float* dec_bih, const float* dec_bhh,
    const float* out_W, const float* out_b,
    float* out, int out_size)
{
    extern __shared__ __align__(16) float sm[];
    const int tid = threadIdx.x;

    // =================== table-builder CTAs (8..51) ===================
    if (blockIdx.x >= 8) {
        int job = (int)blockIdx.x - 8;            // 0..15 enc-t, 16..43 dec-tok
        if (job >= ENCL + NV) return;
        bool enc = job < ENCL;
        const float* emb = enc ? enc_emb + data[job] * HID
                               : dec_emb + (job - ENCL) * HID;
        float* xs = sm;                            // 256 floats
        for (int i = tid; i < 64; i += TPB) {
            float4 v = ((const float4*)emb)[i];
            if (!enc) {
                v.x = fmaxf(v.x, 0.f); v.y = fmaxf(v.y, 0.f);
                v.z = fmaxf(v.z, 0.f); v.w = fmaxf(v.w, 0.f);
            }
            ((float4*)xs)[i] = v;
        }
        __syncthreads();
        const float* W  = enc ? enc_Wih : dec_Wih;
        const float* b1 = enc ? enc_bih : dec_bih;
        const float* b2 = enc ? enc_bhh : dec_bhh;
        float* dst = enc ? g_pre + job * 1024 : g_tab + (job - ENCL) * 1024;
        const int grp = tid >> 3, e = tid & 7;
        const float4* xv = (const float4*)xs + e * 8;
        float4 x0 = xv[0], x1 = xv[1], x2 = xv[2], x3 = xv[3];
        float4 x4 = xv[4], x5 = xv[5], x6 = xv[6], x7 = xv[7];
#pragma unroll 1
        for (int j = 0; j < 16; j += 2) {
            int r0 = grp * 16 + j, r1 = r0 + 1;
            const float4* w0 = (const float4*)(W + r0 * HID) + e * 8;
            const float4* w1 = (const float4*)(W + r1 * HID) + e * 8;
            float s0 = dot8(w0[0], w0[1], x0, x1) + dot8(w0[2], w0[3], x2, x3)
                     + dot8(w0[4], w0[5], x4, x5) + dot8(w0[6], w0[7], x6, x7);
            float s1 = dot8(w1[0], w1[1], x0, x1) + dot8(w1[2], w1[3], x2, x3)
                     + dot8(w1[4], w1[5], x4, x5) + dot8(w1[6], w1[7], x6, x7);
#pragma unroll
            for (int o = 1; o < 8; o <<= 1) {
                s0 += __shfl_xor_sync(0xffffffffu, s0, o);
                s1 += __shfl_xor_sync(0xffffffffu, s1, o);
            }
            if (e == 0) {
                dst[(r0 & 255) * 4 + (r0 >> 8)] = s0 + b1[r0] + b2[r0];
                dst[(r1 & 255) * 4 + (r1 >> 8)] = s1 + b1[r1] + b2[r1];
            }
        }
        __syncthreads();
        if (tid == 0) st_rel_gpu(&g_flag[job], 1);
        return;
    }

    // =================== cluster 0: sequential LSTM ===================
    float* h3b    = sm + O_H3B;
    float* cfull  = sm + O_CF;
    float* pre_sh = sm + O_PRE;
    float* tab_sh = sm + O_TAB;
    float* ow_sh  = sm + O_OW;
    float* cat_h  = sm + O_CATH;
    float* cat_c  = sm + O_CATC;
    float* cnew_sh= sm + O_CNEW;
    volatile ull* wmax_sh = (volatile ull*)(sm + O_WMAX);
    int*   tags   = (int*)(sm + O_TAGS);

    const int w    = tid >> 5;
    const int lane = tid & 31;
    const int s8   = lane & 7;
    const int q    = lane >> 3;
    const int b    = blockIdx.x;                  // cluster rank
    const int L    = lane;
    const int ug   = b * 32 + 2 * w + (L & 1);    // this lane's mirrored unit

    const uint32_t hb    = smem_u32(h3b);
    const uint32_t cfb   = smem_u32(cfull);
    const uint32_t tagsb = smem_u32(tags);

    const int RA = q * HID + b * 32 + 2 * w;      // gate q, unit 2w
    const int RB = RA + 1;

    ull wA[16], wB[16];
    load_wrows(enc_Whh, RA, RB, s8, wA, wB);

    uint32_t hmap[CS];
#pragma unroll
    for (int r = 0; r < CS; r++) hmap[r] = mapa_u32(hb, r);
    uint32_t tagmap = 0;
    if (w == 0 && lane < 8) tagmap = mapa_u32(tagsb, (uint32_t)lane);

    // out_W -> smem (stride-264 rows)
    for (int i = tid; i < NV * 64; i += TPB) {
        int row = i >> 6, c4 = i & 63;
        ((float4*)(ow_sh + row * 264))[c4] = ((const float4*)out_W)[i];
    }
    // L2 prefetch: dec_Whh slice + latent weights
    for (int i = tid; i < 1024; i += TPB) {
        int gi = i >> 8, off = i & 255;
        pf_l2((const char*)(dec_Whh + (gi * 256 + b * 32) * HID) + off * 128);
    }
    for (int i = tid; i < 256; i += TPB) {
        pf_l2((const char*)hmu_W + i * 128);
        pf_l2((const char*)cmu_W + i * 128);
    }
    for (int i = tid; i < 320; i += TPB) {
        pf_l2((const char*)fc1_W + i * 128);
        pf_l2((const char*)fc2_W + i * 128);
    }

    const int lrow = w * 4 + q;
    float obv = (w < 7) ? out_b[lrow] : 0.f;

    const int dcid = data_c[0], tcid = target_c[0];
    if (tid < HID) {
        float v = (tid >= HID - 8) ? cond_emb[dcid * 8 + (tid - (HID - 8))] : 0.f;
        h3b[tid] = v;                              // slot 0
    }
    float creg = (ug >= HID - 8) ? cond_emb[dcid * 8 + (ug - (HID - 8))] : 0.f;
    if (tid < 24) tags[tid] = (tid < 8) ? 0 : -1;

    __syncthreads();
    cluster_bar();

    // wait for encoder projection tables, copy slice
    if (tid < ENCL) while (ld_acq_gpu(&g_flag[tid]) == 0) { }
    __syncthreads();
    for (int i = tid; i < ENCL * 32; i += TPB)
        ((float4*)pre_sh)[i] = ((const float4*)g_pre)[(i >> 5) * 256 + b * 32 + (i & 31)];
    __syncthreads();

    // ================= encoder: N = 0..15 =================
#pragma unroll 1
    for (int n = 0; n < ENCL; n++) {
        int slot = n % 3, slot2 = (n + 1) % 3;
        wait_tags(tagsb, slot, s8, n);
        float sA, sB;
        dual_dot(h3b + slot * HID, s8, wA, wB, sA, sB);
        float a0 = __shfl_sync(0xffffffffu, sA, 0),  a1 = __shfl_sync(0xffffffffu, sA, 8);
        float a2 = __shfl_sync(0xffffffffu, sA, 16), a3 = __shfl_sync(0xffffffffu, sA, 24);
        float b0 = __shfl_sync(0xffffffffu, sB, 0),  b1 = __shfl_sync(0xffffffffu, sB, 8);
        float b2 = __shfl_sync(0xffffffffu, sB, 16), b3 = __shfl_sync(0xffffffffu, sB, 24);
        int sel = L & 1;
        float4 pr = *(const float4*)(pre_sh + n * 128 + (2 * w + sel) * 4);
        float gi = (sel ? b0 : a0) + pr.x;
        float gf = (sel ? b1 : a1) + pr.y;
        float gg = (sel ? b2 : a2) + pr.z;
        float go = (sel ? b3 : a3) + pr.w;
        float c = sigf(gf) * creg + sigf(gi) * tanhfast(gg);
        float h = sigf(go) * tanhfast(c);
        creg = c;
        float hB = __shfl_sync(0xffffffffu, h, 1);
        float cB = __shfl_sync(0xffffffffu, c, 1);
        if (L == 0) {
            ull hp = pack2(h, hB);
            uint32_t off = (uint32_t)((slot2 * HID + b * 32 + 2 * w) * 4);
#pragma unroll
            for (int r = 0; r < CS; r++) st_cluster_b64(hmap[r] + off, hp);
            if (n == ENCL - 1) {
                ull cp = pack2(c, cB);
                uint32_t co = (uint32_t)((b * 32 + 2 * w) * 4);
#pragma unroll
                for (int r = 0; r < CS; r++) st_cluster_b64(mapa_u32(cfb, r) + co, cp);
            }
        }
        __syncthreads();
        if (w == 0 && lane < 8)
            st_rel_cluster_u32(tagmap + (uint32_t)((slot2 * 8 + b) * 4), (uint32_t)(n + 1));
    }

    wait_tags(tagsb, 1, s8, ENCL);                 // hT (slot 1) + cfull arrived

    // ================= latent heads + decoder init =================
    {
        const float4* hv = (const float4*)(h3b + HID) + lane * 2;
        float4 h0v = hv[0], h1v = hv[1];
        const float4* cv = (const float4*)cfull + lane * 2;
        float4 c0v = cv[0], c1v = cv[1];
#pragma unroll
        for (int half = 0; half < 2; half++) {
            int rr = w + half * 16;
            const float4* pp = (const float4*)(hmu_W + rr * HID);
            float4 a0 = pp[lane * 2], a1 = pp[lane * 2 + 1];
            float s = red32(dot8(a0, a1, h0v, h1v));
            if (lane == 0) cat_h[rr] = s + hmu_b[rr];
            pp = (const float4*)(cmu_W + rr * HID);
            a0 = pp[lane * 2]; a1 = pp[lane * 2 + 1];
            s = red32(dot8(a0, a1, c0v, c1v));
            if (lane == 0) cat_c[rr] = s + cmu_b[rr];
        }
    }
    if (tid < 8) {
        float v = cond_emb[tcid * 8 + tid];
        cat_h[32 + tid] = v; cat_c[32 + tid] = v;
    }
    // overlap: warps 9-10 poll decoder-table flags while others do fc dots
    if (tid >= 288 && tid < 288 + NV)
        while (ld_acq_gpu(&g_flag[ENCL + (tid - 288)]) == 0) { }
    __syncthreads();
    float newv = 0.f;
    if (tid < HID) {
        float s = fc1_b[tid];
        const float* wr = fc1_W + tid * 40;
#pragma unroll
        for (int k = 0; k < 40; k++) s += cat_h[k] * wr[k];
        newv = s;
    }
    if (tid < 32) {
        int j = b * 32 + tid;
        float s = fc2_b[j];
        const float* wr = fc2_W + j * 40;
#pragma unroll
        for (int k = 0; k < 40; k++) s += cat_c[k] * wr[k];
        cnew_sh[tid] = s;
    }
    __syncthreads();
    if (tid < HID) h3b[2 * HID + tid] = newv;       // dh -> slot 2 (N=17)
    if (tid < 8) tags[16 + tid] = 17;
    creg = cnew_sh[2 * w + (L & 1)];
    // copy decoder token table slice (flags already confirmed)
    for (int i = tid; i < NV * 32; i += TPB)
        ((float4*)tab_sh)[i] = ((const float4*)g_tab)[(i >> 5) * 256 + b * 32 + (i & 31)];
    load_wrows(dec_Whh, RA, RB, s8, wA, wB);        // L2-warm
    __syncthreads();

    // ================= decoder: N = 17..41 =================
#pragma unroll 1
    for (int m = 0; m < DECL; m++) {
        int N = 17 + m;
        int slot = N % 3, slot2 = (N + 1) % 3;
        wait_tags(tagsb, slot, s8, N);
        const float* hcur = h3b + slot * HID;
        float lg = 0.f;
        if (m > 0 && w < 7) {
            lg = one_dot(hcur, ow_sh + lrow * 264, s8) + obv;
            uint32_t bits = __float_as_uint(lg);
            uint32_t key = (bits & 0x80000000u) ? ~bits : (bits | 0x80000000u);
            ull cmp = ((ull)key << 8) | (ull)(255 - lrow);
#pragma unroll
            for (int o = 8; o <= 16; o <<= 1) {
                ull ot = __shfl_xor_sync(0xffffffffu, cmp, o);
                if (ot > cmp) cmp = ot;
            }
            if (lane == 0) wmax_sh[w] = cmp;
        }
        float sA, sB;
        dual_dot(hcur, s8, wA, wB, sA, sB);
        __syncthreads();
        if (b == 0 && m > 0 && w < 7 && s8 == 0)
            out[(m - 1) * NV + lrow] = lg;
        float a0 = __shfl_sync(0xffffffffu, sA, 0),  a1 = __shfl_sync(0xffffffffu, sA, 8);
        float a2 = __shfl_sync(0xffffffffu, sA, 16), a3 = __shfl_sync(0xffffffffu, sA, 24);
        float b0 = __shfl_sync(0xffffffffu, sB, 0),  b1 = __shfl_sync(0xffffffffu, sB, 8);
        float b2 = __shfl_sync(0xffffffffu, sB, 16), b3 = __shfl_sync(0xffffffffu, sB, 24);
        int tok = 0;
        if (m > 0) {
            ull v = wmax_sh[0];
#pragma unroll
            for (int i = 1; i < 7; i++) { ull ot = wmax_sh[i]; if (ot > v) v = ot; }
            tok = 255 - (int)(v & 0xffu);
            if (b == 0 && w == 7 && L == 0) out[NV * DECL + (m - 1)] = (float)tok;
        }
        int sel = L & 1;
        float4 pr = *(const float4*)(tab_sh + tok * 128 + (2 * w + sel) * 4);
        float gi = (sel ? b0 : a0) + pr.x;
        float gf = (sel ? b1 : a1) + pr.y;
        float gg = (sel ? b2 : a2) + pr.z;
        float go = (sel ? b3 : a3) + pr.w;
        float c = sigf(gf) * creg + sigf(gi) * tanhfast(gg);
        float h = sigf(go) * tanhfast(c);
        creg = c;
        float hB = __shfl_sync(0xffffffffu, h, 1);
        if (L == 0) {
            ull hp = pack2(h, hB);
            uint32_t off = (uint32_t)((slot2 * HID + b * 32 + 2 * w) * 4);
#pragma unroll
            for (int r = 0; r < CS; r++) st_cluster_b64(hmap[r] + off, hp);
        }
        __syncthreads();
        if (w == 0 && lane < 8)
            st_rel_cluster_u32(tagmap + (uint32_t)((slot2 * 8 + b) * 4), (uint32_t)(N + 1));
    }

    // ---- tail: logits/argmax of final step (slot 0, tag 42) ----
    if (b == 0) {
        wait_tags(tagsb, 0, s8, 42);
        const float* hcur = h3b;
        float lg = 0.f;
        if (w < 7) {
            lg = one_dot(hcur, ow_sh + lrow * 264, s8) + obv;
            uint32_t bits = __float_as_uint(lg);
            uint32_t key = (bits & 0x80000000u) ? ~bits : (bits | 0x80000000u);
            ull cmp = ((ull)key << 8) | (ull)(255 - lrow);
#pragma unroll
            for (int o = 8; o <= 16; o <<= 1) {
                ull ot = __shfl_xor_sync(0xffffffffu, cmp, o);
                if (ot > cmp) cmp = ot;
            }
            if (lane == 0) wmax_sh[w] = cmp;
        }
        __syncthreads();
        if (w < 7 && s8 == 0) out[(DECL - 1) * NV + lrow] = lg;
        if (w == 7 && lane == 0) {
            ull v = wmax_sh[0];
#pragma unroll
            for (int i = 1; i < 7; i++) { ull ot = wmax_sh[i]; if (ot > v) v = ot; }
            out[NV * DECL + (DECL - 1)] = (float)(255 - (int)(v & 0xffu));
        }
        // reset flags for the next graph replay (stream-ordered)
        if (tid < ENCL + NV) g_flag[tid] = 0;
    }
    cluster_bar();
    (void)out_size;
}

extern "C" void kernel_launch(void* const* d_in, const int* in_sizes, int n_in,
                              void* d_out, int out_size) {
    (void)in_sizes; (void)n_in;
    const int*   data     = (const int*)  d_in[0];
    const int*   data_c   = (const int*)  d_in[1];
    const int*   target_c = (const int*)  d_in[2];
    const float* cond_emb = (const float*)d_in[3];
    const float* enc_emb  = (const float*)d_in[4];
    const float* enc_Wih  = (const float*)d_in[5];
    const float* enc_Whh  = (const float*)d_in[6];
    const float* enc_bih  = (const float*)d_in[7];
    const float* enc_bhh  = (const float*)d_in[8];
    const float* hmu_W    = (const float*)d_in[9];
    const float* hmu_b    = (const float*)d_in[10];
    const float* cmu_W    = (const float*)d_in[11];
    const float* cmu_b    = (const float*)d_in[12];
    const float* fc1_W    = (const float*)d_in[13];
    const float* fc1_b    = (const float*)d_in[14];
    const float* fc2_W    = (const float*)d_in[15];
    const float* fc2_b    = (const float*)d_in[16];
    const float* dec_emb  = (const float*)d_in[17];
    const float* dec_Wih  = (const float*)d_in[18];
    const float* dec_Whh  = (const float*)d_in[19];
    const float* dec_bih  = (const float*)d_in[20];
    const float* dec_bhh  = (const float*)d_in[21];
    const float* out_W    = (const float*)d_in[22];
    const float* out_b    = (const float*)d_in[23];

    cudaFuncSetAttribute(vae_kernel, cudaFuncAttributeMaxDynamicSharedMemorySize, SMEM_BYTES);
    vae_kernel<<<GRID, TPB, SMEM_BYTES>>>(data, data_c, target_c, cond_emb,
                                          enc_emb, enc_Wih, enc_Whh, enc_bih, enc_bhh,
                                          hmu_W, hmu_b, cmu_W, cmu_b,
                                          fc1_W, fc1_b, fc2_W, fc2_b,
                                          dec_emb, dec_Wih, dec_Whh, dec_bih, dec_bhh,
                                          out_W, out_b,
                                          (float*)d_out, out_size);
}